// round 9
// baseline (speedup 1.0000x reference)
#include <cuda_runtime.h>
#include <cuda_fp16.h>

#define R0_   128
#define R1_   512
#define HW0   (R0_ * R0_)
#define HW1   (R1_ * R1_)
#define BAX   16                  // bins per axis
#define NBIN  (BAX * BAX * BAX)   // 4096
#define MAXN  2200000

// Coarse planes: plain [H*W][32] fp16 (texel = 64B).
__device__ __half g_cxy[HW0 * 32];
__device__ __half g_cxz[HW0 * 32];
__device__ __half g_cyz[HW0 * 32];
// Fine planes: duplicated y-pair blocks (copy P, block k, col x):
//   128B block = 32 x half2( v(row 2k+P, x), v(row 2k+P+1, x) )
__device__ __half2 g_fxy[2 * HW1 * 16];
__device__ __half2 g_fxz[2 * HW1 * 16];
__device__ __half2 g_fyz[2 * HW1 * 16];

// Sort scratch
__device__ int    g_hist[NBIN];
__device__ int    g_cursor[NBIN];
__device__ int    g_start[NBIN + 1];
__device__ float4 g_spts[MAXN];

#define CT0 (HW0 / 32)                    // 512 coarse tiles per plane
#define KB1 ((R1_ / 2) * (R1_ / 32))      // 4096 fine blocks per plane
#define TGRID (3 * CT0 + 3 * KB1)

// ------------- fused transpose: coarse -> plain, fine -> dup-y -------------
__global__ void transpose_all_kernel(const float* __restrict__ in0,
                                     const float* __restrict__ in1,
                                     const float* __restrict__ in2,
                                     const float* __restrict__ in3,
                                     const float* __restrict__ in4,
                                     const float* __restrict__ in5) {
    __shared__ float t0[32][33], t1[32][33], t2[32][33];
    int bid = blockIdx.x;
    int tx = threadIdx.x, ty = threadIdx.y;

    if (bid < 3 * CT0) {                       // coarse: plain [HW][C]
        int plane = bid / CT0;
        int pix0 = (bid % CT0) * 32;
        const float* in = plane == 0 ? in0 : (plane == 1 ? in1 : in2);
        __half* out = plane == 0 ? g_cxy : (plane == 1 ? g_cxz : g_cyz);
#pragma unroll
        for (int cc = 0; cc < 32; cc += 8)
            t0[cc + ty][tx] = in[(cc + ty) * HW0 + pix0 + tx];
        __syncthreads();
#pragma unroll
        for (int pp = 0; pp < 32; pp += 8)
            out[(long)(pix0 + pp + ty) * 32 + tx] = __float2half(t0[tx][pp + ty]);
    } else {                                   // fine: dup y-pair blocks
        int b = bid - 3 * CT0;
        int plane = b / KB1;
        int kidx = b % KB1;
        const int W = R1_, HW = HW1;
        const float* in = plane == 0 ? in3 : (plane == 1 ? in4 : in5);
        __half2* out = plane == 0 ? g_fxy : (plane == 1 ? g_fxz : g_fyz);

        int k = kidx / (W / 32);
        int xbase = (kidx % (W / 32)) * 32;
        int r0 = 2 * k, r1 = 2 * k + 1, r2 = min(2 * k + 2, W - 1);
#pragma unroll
        for (int cc = 0; cc < 32; cc += 8) {
            int c = cc + ty;
            t0[c][tx] = in[(long)c * HW + (long)r0 * W + xbase + tx];
            t1[c][tx] = in[(long)c * HW + (long)r1 * W + xbase + tx];
            t2[c][tx] = in[(long)c * HW + (long)r2 * W + xbase + tx];
        }
        __syncthreads();
        long copyB = (long)(W / 2) * W * 32;
#pragma unroll
        for (int pp = 0; pp < 32; pp += 8) {
            int x = pp + ty;
            long ia = ((long)k * W + xbase + x) * 32 + tx;
            out[ia]         = __floats2half2_rn(t0[tx][x], t1[tx][x]);
            out[copyB + ia] = __floats2half2_rn(t1[tx][x], t2[tx][x]);
        }
    }
}

// ---------------- binning ----------------
__device__ __forceinline__ int bin_of(float v) {
    return min(max((int)((v + 1.0f) * (0.5f * BAX)), 0), BAX - 1);
}
__device__ __forceinline__ int point_key(float x, float y, float z) {
    return (bin_of(z) * BAX + bin_of(y)) * BAX + bin_of(x);
}

__global__ void zero_kernel() {
    int i = blockIdx.x * blockDim.x + threadIdx.x;
    if (i < NBIN) { g_hist[i] = 0; g_cursor[i] = 0; }
}

__global__ void hist_kernel(const float* __restrict__ pts, int n) {
    int i = blockIdx.x * blockDim.x + threadIdx.x;
    if (i >= n) return;
    atomicAdd(&g_hist[point_key(pts[3*i], pts[3*i+1], pts[3*i+2])], 1);
}

// Exclusive scan of 4096 bins: 256 threads x 16 bins each.
__global__ void scan_kernel() {
    __shared__ int psum[256];
    int t = threadIdx.x;
    int base = t * 16;
    int loc[16];
    int s = 0;
#pragma unroll
    for (int k = 0; k < 16; k++) { loc[k] = s; s += g_hist[base + k]; }
    psum[t] = s;
    __syncthreads();
    for (int o = 1; o < 256; o <<= 1) {
        int v = psum[t];
        int a = (t >= o) ? psum[t - o] : 0;
        __syncthreads();
        psum[t] = v + a;
        __syncthreads();
    }
    int offs = (t > 0) ? psum[t - 1] : 0;
#pragma unroll
    for (int k = 0; k < 16; k++) g_start[base + k] = offs + loc[k];
    if (t == 255) g_start[NBIN] = psum[255];
}

__global__ void scatter_kernel(const float* __restrict__ pts, int n) {
    int i = blockIdx.x * blockDim.x + threadIdx.x;
    if (i >= n) return;
    float x = pts[3*i], y = pts[3*i+1], z = pts[3*i+2];
    int key = point_key(x, y, z);
    int pos = g_start[key] + atomicAdd(&g_cursor[key], 1);
    g_spts[pos] = make_float4(x, y, z, __int_as_float(i));
}

// ---------------- sampling helpers ----------------
__device__ __forceinline__ float4 h2f4(uint2 u) {
    __half2 h0 = *(__half2*)&u.x, h1 = *(__half2*)&u.y;
    float2 f0 = __half22float2(h0), f1 = __half22float2(h1);
    return make_float4(f0.x, f0.y, f1.x, f1.y);
}

// Coarse from smem tile (plane pl at tile[pl*400..]); thread t owns ch [4t,4t+4).
__device__ __forceinline__ void coarse_sample(const uint2* __restrict__ T,
                                              int pl, float gx, float gy,
                                              int cb, int rb, int t,
                                              float acc[4]) {
    float ix = fminf(fmaxf((gx + 1.0f) * 63.5f, 0.0f), 127.0f);
    float iy = fminf(fmaxf((gy + 1.0f) * 63.5f, 0.0f), 127.0f);
    int x0 = min((int)ix, 126), y0 = min((int)iy, 126);
    float wx = ix - (float)x0, wy = iy - (float)y0;
    int lx = x0 - cb, ly = y0 - rb;

    int base = ((pl * 10 + ly) * 10 + lx) * 8 + t;
    float4 c00 = h2f4(T[base]);
    float4 c10 = h2f4(T[base + 8]);
    float4 c01 = h2f4(T[base + 80]);
    float4 c11 = h2f4(T[base + 88]);

    float4 v0, v1;
    v0.x = c00.x + wx * (c10.x - c00.x); v1.x = c01.x + wx * (c11.x - c01.x);
    v0.y = c00.y + wx * (c10.y - c00.y); v1.y = c01.y + wx * (c11.y - c01.y);
    v0.z = c00.z + wx * (c10.z - c00.z); v1.z = c01.z + wx * (c11.z - c01.z);
    v0.w = c00.w + wx * (c10.w - c00.w); v1.w = c01.w + wx * (c11.w - c01.w);
    acc[0] += v0.x + wy * (v1.x - v0.x);
    acc[1] += v0.y + wy * (v1.y - v0.y);
    acc[2] += v0.z + wy * (v1.z - v0.z);
    acc[3] += v0.w + wy * (v1.w - v0.w);
}

// Fine from dup-y global blocks; thread t owns ch [4t,4t+4).
__device__ __forceinline__ void fine_sample(const uint4* __restrict__ plane,
                                            float gx, float gy, int t,
                                            float acc[4]) {
    const int R = R1_;
    const float s = 0.5f * (float)(R - 1);
    float ix = fminf(fmaxf((gx + 1.0f) * s, 0.0f), (float)(R - 1));
    float iy = fminf(fmaxf((gy + 1.0f) * s, 0.0f), (float)(R - 1));
    int x0 = min((int)ix, R - 2);
    int y0 = min((int)iy, R - 2);
    float wx = ix - (float)x0;
    float wy = iy - (float)y0;

    int par = y0 & 1;
    int k   = y0 >> 1;
    long brow = ((long)par * (R / 2) + k) * R;

    uint4 A = __ldg(plane + (brow + x0) * 8 + t);
    uint4 B = __ldg(plane + (brow + x0 + 1) * 8 + t);
    const __half2* a = (const __half2*)&A;
    const __half2* b = (const __half2*)&B;
#pragma unroll
    for (int c = 0; c < 4; c++) {
        float2 f0 = __half22float2(a[c]);
        float2 f1 = __half22float2(b[c]);
        float v0 = f0.x + wy * (f0.y - f0.x);
        float v1 = f1.x + wy * (f1.y - f1.x);
        acc[c] += v0 + wx * (v1 - v0);
    }
}

__device__ __forceinline__ int tile_base(int b) { return (b * 127) >> 4; }

// ---------------- binned gather: 1 CTA per bin ----------------
__global__ void __launch_bounds__(256)
gather_bin_kernel(float* __restrict__ out) {
    __shared__ __half tile[3 * 10 * 10 * 32];   // 19.2 KB
    int b = blockIdx.x;
    int bx = b & 15, by = (b >> 4) & 15, bz = b >> 8;
    int cbx = tile_base(bx), cby = tile_base(by), cbz = tile_base(bz);

    // Stage coarse tiles: plane 0 = xy (cols bx, rows by), 1 = xz (bx, bz),
    // 2 = yz (by, bz). 400 uint4 per plane.
    {
        uint4* Td = (uint4*)tile;
#pragma unroll
        for (int pl = 0; pl < 3; pl++) {
            const uint4* src = pl == 0 ? (const uint4*)g_cxy
                             : pl == 1 ? (const uint4*)g_cxz
                                       : (const uint4*)g_cyz;
            int cb = (pl == 2) ? cby : cbx;
            int rb = (pl == 0) ? cby : cbz;
            for (int i = threadIdx.x; i < 400; i += 256) {
                int ly = i / 40;
                int rem = i - ly * 40;
                int lx = rem >> 2;
                int q  = rem & 3;
                int gy = min(rb + ly, 127);
                int gx = min(cb + lx, 127);
                Td[pl * 400 + i] = __ldg(src + ((long)gy * 128 + gx) * 4 + q);
            }
        }
    }
    __syncthreads();

    int s = g_start[b], e = g_start[b + 1];
    int t = threadIdx.x & 7;
    const uint2* T = (const uint2*)tile;

    for (int i = s + (threadIdx.x >> 3); i < e; i += 32) {
        float4 pt = __ldg(&g_spts[i]);
        float x = pt.x, y = pt.y, z = pt.z;
        int oi = __float_as_int(pt.w);

        float ac[4] = {0.f, 0.f, 0.f, 0.f};
        coarse_sample(T, 0, x, y, cbx, cby, t, ac);
        coarse_sample(T, 1, x, z, cbx, cbz, t, ac);
        coarse_sample(T, 2, y, z, cby, cbz, t, ac);

        float af[4] = {0.f, 0.f, 0.f, 0.f};
        fine_sample((const uint4*)g_fxy, x, y, t, af);
        fine_sample((const uint4*)g_fxz, x, z, t, af);
        fine_sample((const uint4*)g_fyz, y, z, t, af);

        float4* o = (float4*)(out + (long)oi * 64);
        o[t]     = make_float4(ac[0], ac[1], ac[2], ac[3]);
        o[8 + t] = make_float4(af[0], af[1], af[2], af[3]);
    }
}

// ---------------- fallback (n > MAXN): direct, no sort ----------------
__global__ void __launch_bounds__(256)
gather_direct_kernel(const float* __restrict__ pts, float* __restrict__ out,
                     int n) {
    long tid = (long)blockIdx.x * blockDim.x + threadIdx.x;
    int p = (int)(tid >> 3);
    int t = (int)(tid & 7);
    if (p >= n) return;
    float x = __ldg(pts + (long)p * 3 + 0);
    float y = __ldg(pts + (long)p * 3 + 1);
    float z = __ldg(pts + (long)p * 3 + 2);

    float ac[4] = {0.f, 0.f, 0.f, 0.f};
    // coarse direct from plain layout
    {
        const uint2* P[3] = {(const uint2*)g_cxy, (const uint2*)g_cxz,
                             (const uint2*)g_cyz};
        float gxs[3] = {x, x, y}, gys[3] = {y, z, z};
#pragma unroll
        for (int pl = 0; pl < 3; pl++) {
            float ix = fminf(fmaxf((gxs[pl] + 1.0f) * 63.5f, 0.0f), 127.0f);
            float iy = fminf(fmaxf((gys[pl] + 1.0f) * 63.5f, 0.0f), 127.0f);
            int x0 = min((int)ix, 126), y0 = min((int)iy, 126);
            float wx = ix - (float)x0, wy = iy - (float)y0;
            long i00 = ((long)y0 * 128 + x0) * 8 + t;
            float4 c00 = h2f4(__ldg(P[pl] + i00));
            float4 c10 = h2f4(__ldg(P[pl] + i00 + 8));
            float4 c01 = h2f4(__ldg(P[pl] + i00 + 1024));
            float4 c11 = h2f4(__ldg(P[pl] + i00 + 1032));
            float v0x = c00.x + wx * (c10.x - c00.x), v1x = c01.x + wx * (c11.x - c01.x);
            float v0y = c00.y + wx * (c10.y - c00.y), v1y = c01.y + wx * (c11.y - c01.y);
            float v0z = c00.z + wx * (c10.z - c00.z), v1z = c01.z + wx * (c11.z - c01.z);
            float v0w = c00.w + wx * (c10.w - c00.w), v1w = c01.w + wx * (c11.w - c01.w);
            ac[0] += v0x + wy * (v1x - v0x);
            ac[1] += v0y + wy * (v1y - v0y);
            ac[2] += v0z + wy * (v1z - v0z);
            ac[3] += v0w + wy * (v1w - v0w);
        }
    }
    float af[4] = {0.f, 0.f, 0.f, 0.f};
    fine_sample((const uint4*)g_fxy, x, y, t, af);
    fine_sample((const uint4*)g_fxz, x, z, t, af);
    fine_sample((const uint4*)g_fyz, y, z, t, af);

    float4* o = (float4*)(out + (long)p * 64);
    o[t]     = make_float4(ac[0], ac[1], ac[2], ac[3]);
    o[8 + t] = make_float4(af[0], af[1], af[2], af[3]);
}

extern "C" void kernel_launch(void* const* d_in, const int* in_sizes, int n_in,
                              void* d_out, int out_size) {
    const float* pts = (const float*)d_in[0];
    int n = in_sizes[0] / 3;

    dim3 tb(32, 8);
    transpose_all_kernel<<<TGRID, tb>>>(
        (const float*)d_in[1], (const float*)d_in[2], (const float*)d_in[3],
        (const float*)d_in[4], (const float*)d_in[5], (const float*)d_in[6]);

    if (n <= MAXN) {
        zero_kernel<<<(NBIN + 255) / 256, 256>>>();
        hist_kernel<<<(n + 255) / 256, 256>>>(pts, n);
        scan_kernel<<<1, 256>>>();
        scatter_kernel<<<(n + 255) / 256, 256>>>(pts, n);
        gather_bin_kernel<<<NBIN, 256>>>((float*)d_out);
    } else {
        long total = (long)n * 8;
        int blocks = (int)((total + 255) / 256);
        gather_direct_kernel<<<blocks, 256>>>(pts, (float*)d_out, n);
    }
}

// round 10
// speedup vs baseline: 1.2349x; 1.2349x over previous
#include <cuda_runtime.h>
#include <cuda_fp16.h>

#define R0_   128
#define R1_   512
#define HW0   (R0_ * R0_)
#define HW1   (R1_ * R1_)

// All planes as duplicated y-pair blocks:
//   copy P (P=0,1), block k in [0,R/2), column x:
//     128B block = 32 x half2( v(row 2k+P, x), v(row min(2k+P+1,R-1), x) )
// half2 index: ((P*(R/2) + k)*R + x)*32 + c
__device__ __half2 g_xy0[2 * HW0 * 16];
__device__ __half2 g_xz0[2 * HW0 * 16];
__device__ __half2 g_yz0[2 * HW0 * 16];
__device__ __half2 g_xy1[2 * HW1 * 16];
__device__ __half2 g_xz1[2 * HW1 * 16];
__device__ __half2 g_yz1[2 * HW1 * 16];

// Transpose grid: block = one k (output row-pair) x 64 columns.
#define KT0 ((R0_ / 2) * (R0_ / 64))      // 128 blocks per coarse plane
#define KT1 ((R1_ / 2) * (R1_ / 64))      // 2048 blocks per fine plane
#define KT_ALL (3 * KT0 + 3 * KT1)        // 6528

__global__ void transpose_all_kernel(const float* __restrict__ in0,
                                     const float* __restrict__ in1,
                                     const float* __restrict__ in2,
                                     const float* __restrict__ in3,
                                     const float* __restrict__ in4,
                                     const float* __restrict__ in5) {
    __shared__ float t0[32][65], t1[32][65], t2[32][65];
    int bid = blockIdx.x;
    int tx = threadIdx.x, ty = threadIdx.y;

    const float* in;
    __half2* out;
    int W, kidx;
    if (bid < 3 * KT0) {
        int plane = bid / KT0;
        kidx = bid % KT0;
        W = R0_;
        in  = plane == 0 ? in0 : (plane == 1 ? in1 : in2);
        out = plane == 0 ? g_xy0 : (plane == 1 ? g_xz0 : g_yz0);
    } else {
        int b = bid - 3 * KT0;
        int plane = b / KT1;
        kidx = b % KT1;
        W = R1_;
        in  = plane == 0 ? in3 : (plane == 1 ? in4 : in5);
        out = plane == 0 ? g_xy1 : (plane == 1 ? g_xz1 : g_yz1);
    }
    int HW = W * W;
    int xtiles = W / 64;
    int k = kidx / xtiles;
    int xbase = (kidx % xtiles) * 64;
    int r0 = 2 * k, r1 = 2 * k + 1, r2 = min(2 * k + 2, W - 1);

    // Load 3 rows x 64 columns x 32 channels with float2.
#pragma unroll
    for (int cc = 0; cc < 32; cc += 8) {
        int c = cc + ty;
        const float2* p0 = (const float2*)(in + (long)c * HW + (long)r0 * W + xbase);
        const float2* p1 = (const float2*)(in + (long)c * HW + (long)r1 * W + xbase);
        const float2* p2 = (const float2*)(in + (long)c * HW + (long)r2 * W + xbase);
        float2 v0 = p0[tx], v1 = p1[tx], v2 = p2[tx];
        t0[c][2 * tx] = v0.x; t0[c][2 * tx + 1] = v0.y;
        t1[c][2 * tx] = v1.x; t1[c][2 * tx + 1] = v1.y;
        t2[c][2 * tx] = v2.x; t2[c][2 * tx + 1] = v2.y;
    }
    __syncthreads();

    long copyB = (long)(W / 2) * W * 32;   // half2 offset of copy 1
#pragma unroll
    for (int xx = 0; xx < 64; xx += 8) {
        int x = xx + ty;
        long ia = ((long)k * W + xbase + x) * 32 + tx;
        out[ia]         = __floats2half2_rn(t0[tx][x], t1[tx][x]);
        out[copyB + ia] = __floats2half2_rn(t1[tx][x], t2[tx][x]);
    }
}

// Sample one plane for 4 channels. plane viewed as uint4; block = 8 uint4.
// Thread t (0..7) owns channels [4t, 4t+4).
template <int R>
__device__ __forceinline__ void sample_plane(const uint4* __restrict__ plane,
                                             float gx, float gy, int t,
                                             float acc[4]) {
    const float s = 0.5f * (float)(R - 1);
    float ix = fminf(fmaxf((gx + 1.0f) * s, 0.0f), (float)(R - 1));
    float iy = fminf(fmaxf((gy + 1.0f) * s, 0.0f), (float)(R - 1));
    int x0 = min((int)ix, R - 2);
    int y0 = min((int)iy, R - 2);
    float wx = ix - (float)x0;
    float wy = iy - (float)y0;

    int par = y0 & 1;
    int k   = y0 >> 1;
    long brow = ((long)par * (R / 2) + k) * R;

    uint4 A = __ldg(plane + (brow + x0) * 8 + t);       // x0: (y0,y1)
    uint4 B = __ldg(plane + (brow + x0 + 1) * 8 + t);   // x1
    const __half2* a = (const __half2*)&A;
    const __half2* b = (const __half2*)&B;
#pragma unroll
    for (int c = 0; c < 4; c++) {
        float2 f0 = __half22float2(a[c]);
        float2 f1 = __half22float2(b[c]);
        float v0 = f0.x + wy * (f0.y - f0.x);
        float v1 = f1.x + wy * (f1.y - f1.x);
        acc[c] += v0 + wx * (v1 - v0);
    }
}

// Merged gather: 8 threads per point; thread t owns channels [4t,4t+4) of
// both levels. One pts read, 12 LDG.128, 2 streaming STG.128 per thread.
__global__ void __launch_bounds__(256)
gather_kernel(const float* __restrict__ pts, float* __restrict__ out, int n) {
    long tid = (long)blockIdx.x * blockDim.x + threadIdx.x;
    int p = (int)(tid >> 3);
    int t = (int)(tid & 7);
    if (p >= n) return;

    float x = __ldg(pts + (long)p * 3 + 0);
    float y = __ldg(pts + (long)p * 3 + 1);
    float z = __ldg(pts + (long)p * 3 + 2);

    float ac[4] = {0.f, 0.f, 0.f, 0.f};
    sample_plane<R0_>((const uint4*)g_xy0, x, y, t, ac);
    sample_plane<R0_>((const uint4*)g_xz0, x, z, t, ac);
    sample_plane<R0_>((const uint4*)g_yz0, y, z, t, ac);

    float af[4] = {0.f, 0.f, 0.f, 0.f};
    sample_plane<R1_>((const uint4*)g_xy1, x, y, t, af);
    sample_plane<R1_>((const uint4*)g_xz1, x, z, t, af);
    sample_plane<R1_>((const uint4*)g_yz1, y, z, t, af);

    float4* o = (float4*)(out + (long)p * 64);
    __stcs(&o[t],     make_float4(ac[0], ac[1], ac[2], ac[3]));
    __stcs(&o[8 + t], make_float4(af[0], af[1], af[2], af[3]));
}

extern "C" void kernel_launch(void* const* d_in, const int* in_sizes, int n_in,
                              void* d_out, int out_size) {
    const float* pts = (const float*)d_in[0];
    int n = in_sizes[0] / 3;

    dim3 tb(32, 8);
    transpose_all_kernel<<<KT_ALL, tb>>>(
        (const float*)d_in[1], (const float*)d_in[2], (const float*)d_in[3],
        (const float*)d_in[4], (const float*)d_in[5], (const float*)d_in[6]);

    int threads = 256;
    long total = (long)n * 8;
    int blocks = (int)((total + threads - 1) / threads);
    gather_kernel<<<blocks, threads>>>(pts, (float*)d_out, n);
}

// round 11
// speedup vs baseline: 1.3863x; 1.1226x over previous
#include <cuda_runtime.h>
#include <cuda_fp16.h>

#define R0_   128
#define R1_   512
#define HW0   (R0_ * R0_)
#define HW1   (R1_ * R1_)

// All planes as duplicated y-pair blocks:
//   copy P (P=0,1), block k in [0,R/2), column x:
//     128B block = 32 x half2( v(row 2k+P, x), v(row min(2k+P+1,R-1), x) )
__device__ __half2 g_xy0[2 * HW0 * 16];
__device__ __half2 g_xz0[2 * HW0 * 16];
__device__ __half2 g_yz0[2 * HW0 * 16];
__device__ __half2 g_xy1[2 * HW1 * 16];
__device__ __half2 g_xz1[2 * HW1 * 16];
__device__ __half2 g_yz1[2 * HW1 * 16];

#define KT0 ((R0_ / 2) * (R0_ / 64))      // 128 blocks per coarse plane
#define KT1 ((R1_ / 2) * (R1_ / 64))      // 2048 blocks per fine plane
#define KT_ALL (3 * KT0 + 3 * KT1)

__global__ void transpose_all_kernel(const float* __restrict__ in0,
                                     const float* __restrict__ in1,
                                     const float* __restrict__ in2,
                                     const float* __restrict__ in3,
                                     const float* __restrict__ in4,
                                     const float* __restrict__ in5) {
    __shared__ float t0[32][65], t1[32][65], t2[32][65];
    int bid = blockIdx.x;
    int tx = threadIdx.x, ty = threadIdx.y;

    const float* in;
    __half2* out;
    int W, kidx;
    if (bid < 3 * KT0) {
        int plane = bid / KT0;
        kidx = bid % KT0;
        W = R0_;
        in  = plane == 0 ? in0 : (plane == 1 ? in1 : in2);
        out = plane == 0 ? g_xy0 : (plane == 1 ? g_xz0 : g_yz0);
    } else {
        int b = bid - 3 * KT0;
        int plane = b / KT1;
        kidx = b % KT1;
        W = R1_;
        in  = plane == 0 ? in3 : (plane == 1 ? in4 : in5);
        out = plane == 0 ? g_xy1 : (plane == 1 ? g_xz1 : g_yz1);
    }
    int HW = W * W;
    int xtiles = W / 64;
    int k = kidx / xtiles;
    int xbase = (kidx % xtiles) * 64;
    int r0 = 2 * k, r1 = 2 * k + 1, r2 = min(2 * k + 2, W - 1);

#pragma unroll
    for (int cc = 0; cc < 32; cc += 8) {
        int c = cc + ty;
        const float2* p0 = (const float2*)(in + (long)c * HW + (long)r0 * W + xbase);
        const float2* p1 = (const float2*)(in + (long)c * HW + (long)r1 * W + xbase);
        const float2* p2 = (const float2*)(in + (long)c * HW + (long)r2 * W + xbase);
        float2 v0 = p0[tx], v1 = p1[tx], v2 = p2[tx];
        t0[c][2 * tx] = v0.x; t0[c][2 * tx + 1] = v0.y;
        t1[c][2 * tx] = v1.x; t1[c][2 * tx + 1] = v1.y;
        t2[c][2 * tx] = v2.x; t2[c][2 * tx + 1] = v2.y;
    }
    __syncthreads();

    long copyB = (long)(W / 2) * W * 32;
#pragma unroll
    for (int xx = 0; xx < 64; xx += 8) {
        int x = xx + ty;
        long ia = ((long)k * W + xbase + x) * 32 + tx;
        out[ia]         = __floats2half2_rn(t0[tx][x], t1[tx][x]);
        out[copyB + ia] = __floats2half2_rn(t1[tx][x], t2[tx][x]);
    }
}

// Sample one plane for 4 channels; thread t (0..7) owns channels [4t, 4t+4).
// x-lerp in half2 SIMD (lanes = (y0,y1)), y-lerp + accumulation in fp32.
// All index math in 32-bit (offsets < 2^31).
template <int R>
__device__ __forceinline__ void sample_plane(const uint4* __restrict__ plane,
                                             float gx, float gy, int t,
                                             float acc[4]) {
    const float s = 0.5f * (float)(R - 1);
    float ix = fminf(fmaxf((gx + 1.0f) * s, 0.0f), (float)(R - 1));
    float iy = fminf(fmaxf((gy + 1.0f) * s, 0.0f), (float)(R - 1));
    int x0 = min((int)ix, R - 2);
    int y0 = min((int)iy, R - 2);
    float wx = ix - (float)x0;
    float wy = iy - (float)y0;

    int par = y0 & 1;
    int k   = y0 >> 1;
    int idx = ((par * (R / 2) + k) * R + x0) * 8 + t;

    uint4 A = __ldg(plane + idx);        // x0: (y0,y1) per channel
    uint4 B = __ldg(plane + idx + 8);    // x1
    const __half2* a = (const __half2*)&A;
    const __half2* b = (const __half2*)&B;

    __half2 wx2 = __float2half2_rn(wx);
#pragma unroll
    for (int c = 0; c < 4; c++) {
        __half2 m = __hfma2(wx2, __hsub2(b[c], a[c]), a[c]);  // x-lerp (SIMD)
        float2 f = __half22float2(m);                          // (v(y0), v(y1))
        acc[c] += f.x + wy * (f.y - f.x);                      // y-lerp fp32
    }
}

// Coarse gather: 8 threads/point, writes out floats [0,32).
__global__ void __launch_bounds__(256)
gather_coarse_kernel(const float* __restrict__ pts, float* __restrict__ out,
                     int n) {
    long tid = (long)blockIdx.x * blockDim.x + threadIdx.x;
    int p = (int)(tid >> 3);
    int t = (int)(tid & 7);
    if (p >= n) return;

    float x = __ldg(pts + (long)p * 3 + 0);
    float y = __ldg(pts + (long)p * 3 + 1);
    float z = __ldg(pts + (long)p * 3 + 2);

    float a[4] = {0.f, 0.f, 0.f, 0.f};
    sample_plane<R0_>((const uint4*)g_xy0, x, y, t, a);
    sample_plane<R0_>((const uint4*)g_xz0, x, z, t, a);
    sample_plane<R0_>((const uint4*)g_yz0, y, z, t, a);

    float4* o = (float4*)(out + (long)p * 64);
    o[t] = make_float4(a[0], a[1], a[2], a[3]);
}

// Fine gather: 8 threads/point, writes out floats [32,64).
__global__ void __launch_bounds__(256)
gather_fine_kernel(const float* __restrict__ pts, float* __restrict__ out,
                   int n) {
    long tid = (long)blockIdx.x * blockDim.x + threadIdx.x;
    int p = (int)(tid >> 3);
    int t = (int)(tid & 7);
    if (p >= n) return;

    float x = __ldg(pts + (long)p * 3 + 0);
    float y = __ldg(pts + (long)p * 3 + 1);
    float z = __ldg(pts + (long)p * 3 + 2);

    float a[4] = {0.f, 0.f, 0.f, 0.f};
    sample_plane<R1_>((const uint4*)g_xy1, x, y, t, a);
    sample_plane<R1_>((const uint4*)g_xz1, x, z, t, a);
    sample_plane<R1_>((const uint4*)g_yz1, y, z, t, a);

    float4* o = (float4*)(out + (long)p * 64);
    o[8 + t] = make_float4(a[0], a[1], a[2], a[3]);
}

extern "C" void kernel_launch(void* const* d_in, const int* in_sizes, int n_in,
                              void* d_out, int out_size) {
    const float* pts = (const float*)d_in[0];
    int n = in_sizes[0] / 3;

    dim3 tb(32, 8);
    transpose_all_kernel<<<KT_ALL, tb>>>(
        (const float*)d_in[1], (const float*)d_in[2], (const float*)d_in[3],
        (const float*)d_in[4], (const float*)d_in[5], (const float*)d_in[6]);

    int threads = 256;
    long total = (long)n * 8;
    int blocks = (int)((total + threads - 1) / threads);
    gather_fine_kernel<<<blocks, threads>>>(pts, (float*)d_out, n);
    gather_coarse_kernel<<<blocks, threads>>>(pts, (float*)d_out, n);
}